// round 11
// baseline (speedup 1.0000x reference)
#include <cuda_runtime.h>
#include <cuda_fp16.h>
#include <cstdint>

#define BATCH 4
#define SEQ   2048
#define CDIM  2048
#define NH    16
#define DK    128
#define BH    (BATCH*NH)          /* 64  */
#define BTC   (BATCH*SEQ*CDIM)    /* 16777216 */

// Scratch (static device arrays: sanctioned scratch mechanism, no allocs)
__device__ __align__(16) __half g_Xh [(size_t)BTC];         // x fp16      (32 MB)
__device__ __align__(16) __half g_WAh[(size_t)3*CDIM*CDIM]; // w_attn fp16 (24 MB)
__device__ __align__(16) __half g_WPh[(size_t)CDIM*CDIM];   // w_proj fp16 ( 8 MB)
__device__ __align__(16) __half g_Qh [(size_t)BH*SEQ*DK];   // Q fp16 (pre-scaled) [b,h,t,d]
__device__ __align__(16) __half g_Kh [(size_t)BH*SEQ*DK];   // K fp16 [b,h,t,d]
__device__ __align__(16) __half g_Vh [(size_t)BH*SEQ*DK];   // V fp16 [b,h,t,d]
__device__ __align__(16) __half g_Yh [(size_t)BTC];         // attn out fp16 [b,t,c]

#define QSCALE 0.1275310112f      /* log2e / sqrt(128), folded into Q scratch */

__device__ __forceinline__ unsigned packh2(float lo, float hi){
    unsigned d; asm("cvt.rn.f16x2.f32 %0, %1, %2;" : "=r"(d) : "f"(hi), "f"(lo)); return d;
}
__device__ __forceinline__ unsigned hex2(unsigned x){
    unsigned y; asm("ex2.approx.f16x2 %0, %1;" : "=r"(y) : "r"(x)); return y;
}
__device__ __forceinline__ float ex2f(float x){
    float y; asm("ex2.approx.f32 %0, %1;" : "=f"(y) : "f"(x)); return y;
}
__device__ __forceinline__ void mma16(float* c, unsigned a0, unsigned a1, unsigned a2,
                                      unsigned a3, unsigned b0, unsigned b1){
    asm volatile("mma.sync.aligned.m16n8k16.row.col.f32.f16.f16.f32 "
        "{%0,%1,%2,%3}, {%4,%5,%6,%7}, {%8,%9}, {%0,%1,%2,%3};\n"
        : "+f"(c[0]), "+f"(c[1]), "+f"(c[2]), "+f"(c[3])
        : "r"(a0), "r"(a1), "r"(a2), "r"(a3), "r"(b0), "r"(b1));
}
__device__ __forceinline__ void ldsm4(unsigned* r, unsigned addr){
    asm volatile("ldmatrix.sync.aligned.m8n8.x4.shared.b16 {%0,%1,%2,%3}, [%4];"
        : "=r"(r[0]), "=r"(r[1]), "=r"(r[2]), "=r"(r[3]) : "r"(addr));
}
__device__ __forceinline__ void ldsm4t(unsigned* r, unsigned addr){
    asm volatile("ldmatrix.sync.aligned.m8n8.x4.trans.shared.b16 {%0,%1,%2,%3}, [%4];"
        : "=r"(r[0]), "=r"(r[1]), "=r"(r[2]), "=r"(r[3]) : "r"(addr));
}
__device__ __forceinline__ void cpa(unsigned dst, const void* src){
    asm volatile("cp.async.cg.shared.global [%0], [%1], 16;\n" :: "r"(dst), "l"(src));
}
__device__ __forceinline__ void cpcommit(){ asm volatile("cp.async.commit_group;\n"); }
template<int N> __device__ __forceinline__ void cpwait(){
    asm volatile("cp.async.wait_group %0;\n" :: "n"(N));
}
// half index into a [rows][128 halfs] fp16 tile (256B rows), 16B-group xor swizzle
__device__ __forceinline__ int swh(int r, int h){
    int g = h >> 3;
    return r*128 + (((g & 8) | ((g & 7) ^ (r & 7))) << 3) + (h & 7);
}

// ===================== fused fp32 -> fp16 conversion (x, w_attn, w_proj) ============
__global__ void __launch_bounds__(256)
cvt_all(const float* __restrict__ x, const float* __restrict__ wa,
        const float* __restrict__ wp,
        __half* __restrict__ xo, __half* __restrict__ wao, __half* __restrict__ wpo)
{
    const int b = blockIdx.x;
    const float* in; __half* out; size_t off;
    if (b < 8192)       { in = x;  out = xo;  off = (size_t)b*2048; }
    else if (b < 14336) { in = wa; out = wao; off = (size_t)(b-8192)*2048; }
    else                { in = wp; out = wpo; off = (size_t)(b-14336)*2048; }
    const size_t i = off + (size_t)threadIdx.x*8;
    float4 a = *(const float4*)(in + i);
    float4 c = *(const float4*)(in + i + 4);
    uint4 o = make_uint4(packh2(a.x,a.y), packh2(a.z,a.w), packh2(c.x,c.y), packh2(c.z,c.w));
    *(uint4*)(out + i) = o;
}

// ===================== fp16 GEMM: 256x128 tile, 512 thr, 3-stage cp.async ===========
// D = A[256rows,2048] @ B[128rows,2048]^T + bias. 16 warps as 8(m)x2(n), warp 32x64.
// cp.async per chunk: A 32KB + B 16KB = 48KB (25% less than 2x128x128 CTAs).
// A-fragments double-buffered across k16 steps.
// MODE 0: QKV -> Q fp16 (pre-scaled) / K fp32+fp16 / V fp32+fp16.  MODE 1: proj -> fp32.
template<int MODE>
__global__ void __launch_bounds__(512, 1)
gemm_h(const __half* __restrict__ Ag, const __half* __restrict__ Bg,
       const float* __restrict__ bias,
       float* __restrict__ F0, float* __restrict__ F1, float* __restrict__ F2,
       __half* __restrict__ H0, __half* __restrict__ H1, __half* __restrict__ H2)
{
    extern __shared__ __half sh[];   // 3 stages x (A 256x64 | B 128x64) halfs = 144KB
    const unsigned sb = (unsigned)__cvta_generic_to_shared(sh);
    const int tid  = threadIdx.x;
    const int lane = tid & 31, w = tid >> 5;
    const int wm = w >> 1, wn = w & 1;           // 8(m) x 2(n)
    const int lr = lane >> 2, lk = lane & 3;
    const int mBase = blockIdx.y*256, nBase = blockIdx.x*128;

    const __half* A = Ag + (size_t)mBase*2048;
    const __half* B = Bg + (size_t)nBase*2048;

    const int l15 = lane & 15;
    int aRow[2], bRow[4];
    #pragma unroll
    for (int mt=0; mt<2; ++mt) aRow[mt] = wm*32 + mt*16 + l15;
    #pragma unroll
    for (int np=0; np<4; ++np) bRow[np] = wn*64 + np*16 + ((lane>>4)<<3) + (lane&7);
    const int gA = lane >> 4, gB = (lane >> 3) & 1;

    float acc[2][8][4];
    #pragma unroll
    for (int mt=0; mt<2; ++mt)
      #pragma unroll
      for (int nt=0; nt<8; ++nt)
        #pragma unroll
        for (int i=0; i<4; ++i) acc[mt][nt][i] = 0.f;

    auto issue = [&](int slot, int kt){
        const unsigned st = sb + (unsigned)slot*49152u;
        #pragma unroll
        for (int i=0;i<4;++i){                    // A: 256 rows x 64 halfs = 32KB
            int idx = tid + i*512, r = idx>>3, g = idx&7;
            cpa(st + (unsigned)(r*128) + (unsigned)((g^(r&7))<<4),
                A + (size_t)r*2048 + kt*64 + g*8);
        }
        #pragma unroll
        for (int i=0;i<2;++i){                    // B: 128 rows x 64 halfs = 16KB
            int idx = tid + i*512, r = idx>>3, g = idx&7;
            cpa(st + 32768u + (unsigned)(r*128) + (unsigned)((g^(r&7))<<4),
                B + (size_t)r*2048 + kt*64 + g*8);
        }
    };

    issue(0,0); cpcommit();
    issue(1,1); cpcommit();

    const int KT = 32;
    for (int kt=0; kt<KT; ++kt){
        cpwait<1>();
        __syncthreads();
        const unsigned stA = sb + (unsigned)(kt%3)*49152u;
        const unsigned stB = stA + 32768u;

        unsigned afA[2][2][4];   // [buf][mt][4] A fragments, double-buffered over ks
        #pragma unroll
        for (int mt=0; mt<2; ++mt)
            ldsm4(afA[0][mt], stA + (unsigned)(aRow[mt]*128) + (unsigned)((gA^(aRow[mt]&7))<<4));

        #pragma unroll
        for (int ks=0; ks<4; ++ks){
            unsigned bf[4][4];
            #pragma unroll
            for (int np=0; np<4; ++np)
                ldsm4(bf[np], stB + (unsigned)(bRow[np]*128) + (unsigned)(((2*ks+gB)^(bRow[np]&7))<<4));
            if (ks < 3){
                #pragma unroll
                for (int mt=0; mt<2; ++mt)
                    ldsm4(afA[(ks+1)&1][mt],
                          stA + (unsigned)(aRow[mt]*128) + (unsigned)(((2*(ks+1)+gA)^(aRow[mt]&7))<<4));
            }
            const unsigned (*af)[4] = afA[ks&1];
            #pragma unroll
            for (int mt=0; mt<2; ++mt)
                #pragma unroll
                for (int nt=0; nt<8; ++nt)
                    mma16(acc[mt][nt], af[mt][0], af[mt][1], af[mt][2], af[mt][3],
                          bf[nt>>1][2*(nt&1)], bf[nt>>1][2*(nt&1)+1]);
        }
        if (kt+2 < KT) issue((kt+2)%3, kt+2);
        cpcommit();
    }

    // epilogue: paired stores (col, col+1 contiguous)
    #pragma unroll
    for (int mt=0; mt<2; ++mt)
      #pragma unroll
      for (int nt=0; nt<8; ++nt){
        const int row0 = mBase + wm*32 + mt*16 + lr;
        const int col  = nBase + wn*64 + nt*8 + 2*lk;
        float2 bv = *(const float2*)(bias + col);
        const float v00 = acc[mt][nt][0] + bv.x, v01 = acc[mt][nt][1] + bv.y;
        const float v10 = acc[mt][nt][2] + bv.x, v11 = acc[mt][nt][3] + bv.y;
        #pragma unroll
        for (int half=0; half<2; ++half){
            const int m = row0 + half*8;
            const float v0 = half ? v10 : v00, v1 = half ? v11 : v01;
            if (MODE == 0){
                const int bb = m >> 11, t = m & 2047;
                if (col < 2048){
                    const size_t idx = ((size_t)((bb*16 + (col>>7))*2048 + t))*128 + (col & 127);
                    *(unsigned*)(H0 + idx) = packh2(v0*QSCALE, v1*QSCALE);   // Q fp16 scaled
                } else if (col < 4096){
                    const int o = col - 2048;
                    const size_t idx = ((size_t)((bb*16 + (o>>7))*2048 + t))*128 + (o & 127);
                    *(float2*)(F1 + idx) = make_float2(v0, v1);              // K fp32 out
                    *(unsigned*)(H1 + idx) = packh2(v0, v1);                 // K fp16
                } else {
                    const int o = col - 4096;
                    const size_t idx = ((size_t)((bb*16 + (o>>7))*2048 + t))*128 + (o & 127);
                    *(float2*)(F2 + idx) = make_float2(v0, v1);              // V fp32 out
                    *(unsigned*)(H2 + idx) = packh2(v0, v1);                 // V fp16
                }
            } else {
                *(float2*)(F0 + (size_t)m*CDIM + col) = make_float2(v0, v1);
            }
        }
      }
}

// ===================== Fused flash attention (fp16 ops; f16x2 ex2; MMA row-sum) =====
// CTA = (q-tile 128 rows, bh). 8 warps; warp w owns q rows [16w,16w+16).
// smem: sQ 32KB | sK[2] 32KB each | sV[2] 32KB each = 160KB. Double-buffered KV stream.
__global__ void __launch_bounds__(256, 1)
flash_attn(const __half* __restrict__ Qg_, const __half* __restrict__ Kg_,
           const __half* __restrict__ Vg_, __half* __restrict__ Yg)
{
    const int qtile = 15 - blockIdx.y;   // strict long-first launch order
    const int bh    = blockIdx.x;
    const int tid   = threadIdx.x;
    const int lane  = tid & 31, w = tid >> 5;
    const int lr    = lane >> 2, lk = lane & 3;
    const int wrow  = w * 16;
    const unsigned ONES = 0x3C003C00u;   // f16x2 (1.0, 1.0)

    extern __shared__ __half smh[];
    __half* sQh = smh;
    const unsigned sb  = (unsigned)__cvta_generic_to_shared(smh);
    const unsigned sbK = sb + 32768u;     // two 32KB K slots
    const unsigned sbV = sb + 98304u;     // two 32KB V slots

    const __half* Qg = Qg_ + (size_t)bh*SEQ*DK + (size_t)qtile*16384;
    const __half* Kg = Kg_ + (size_t)bh*SEQ*DK;
    const __half* Vg = Vg_ + (size_t)bh*SEQ*DK;

    auto issueKV = [&](int j){
        if (j <= qtile){
            const __half* Kj = Kg + (size_t)j*16384;
            const __half* Vj = Vg + (size_t)j*16384;
            const unsigned dK = sbK + (unsigned)(j&1)*32768u;
            const unsigned dV = sbV + (unsigned)(j&1)*32768u;
            #pragma unroll
            for (int i=0;i<8;++i){
                int idx = tid + i*256, r = idx>>4, g = idx&15;
                unsigned sw = (unsigned)((g&8)|((g&7)^(r&7)));
                cpa(dK + (unsigned)(r*256) + sw*16u, Kj + r*128 + g*8);
                cpa(dV + (unsigned)(r*256) + sw*16u, Vj + r*128 + g*8);
            }
        }
        cpcommit();
    };
    issueKV(0);
    issueKV(1);

    // stage Q (fp16 global -> swizzled smem)
    #pragma unroll
    for (int i=0;i<8;++i){
        int idx = tid + i*256, r = idx>>4, g = idx&15;
        int sw = (g&8)|((g&7)^(r&7));
        *(uint4*)&sQh[r*128 + sw*8] = *(const uint4*)(Qg + r*128 + g*8);
    }
    __syncthreads();

    // hoist Q fragments (reused across all kv tiles)
    unsigned qf[8][4];
    #pragma unroll
    for (int ks=0;ks<8;++ks){
        const int row = wrow + (lane & 15);
        const int h   = ks*16 + (lane>>4)*8;
        ldsm4(qf[ks], sb + 2u*(unsigned)swh(row, h));
    }

    float m0=-1e30f, m1=-1e30f, l0=0.f, l1=0.f;
    float O[16][4];
    #pragma unroll
    for (int nt=0; nt<16; ++nt){ O[nt][0]=0.f; O[nt][1]=0.f; O[nt][2]=0.f; O[nt][3]=0.f; }

    for (int j = 0; j <= qtile; ++j){
        cpwait<1>();
        __syncthreads();
        const unsigned bK = sbK + (unsigned)(j&1)*32768u;
        const unsigned bV = sbV + (unsigned)(j&1)*32768u;

        // S = Q K^T  (Q pre-scaled by log2e/sqrt(dk); pairwise ldsm)
        float S[16][4];
        #pragma unroll
        for (int nt=0; nt<16; ++nt){ S[nt][0]=0.f; S[nt][1]=0.f; S[nt][2]=0.f; S[nt][3]=0.f; }
        #pragma unroll
        for (int ks=0; ks<8; ++ks){
            #pragma unroll
            for (int np=0; np<8; np+=2){
                unsigned k0[4], k1[4];
                const int row0 = np*16 + ((lane>>4)<<3) + (lane&7);
                const int h    = ks*16 + ((lane>>3)&1)*8;
                ldsm4(k0, bK + 2u*(unsigned)swh(row0,      h));
                ldsm4(k1, bK + 2u*(unsigned)swh(row0 + 16, h));
                mma16(S[2*np],   qf[ks][0],qf[ks][1],qf[ks][2],qf[ks][3], k0[0], k0[1]);
                mma16(S[2*np+1], qf[ks][0],qf[ks][1],qf[ks][2],qf[ks][3], k0[2], k0[3]);
                mma16(S[2*np+2], qf[ks][0],qf[ks][1],qf[ks][2],qf[ks][3], k1[0], k1[1]);
                mma16(S[2*np+3], qf[ks][0],qf[ks][1],qf[ks][2],qf[ks][3], k1[2], k1[3]);
            }
        }

        // causal mask on diagonal tile
        if (j == qtile){
            #pragma unroll
            for (int nt=0; nt<16; ++nt){
                const int c0 = nt*8 + 2*lk, c1 = c0 + 1;
                const int r0 = wrow + lr,   r1 = r0 + 8;
                if (c0 > r0) S[nt][0] = -1e30f;
                if (c1 > r0) S[nt][1] = -1e30f;
                if (c0 > r1) S[nt][2] = -1e30f;
                if (c1 > r1) S[nt][3] = -1e30f;
            }
        }

        // online softmax: fp32 max-reduce, then f16x2 ex2 (P lands packed for PV)
        float mx0 = -1e30f, mx1 = -1e30f;
        #pragma unroll
        for (int nt=0; nt<16; ++nt){
            mx0 = fmaxf(mx0, fmaxf(S[nt][0], S[nt][1]));
            mx1 = fmaxf(mx1, fmaxf(S[nt][2], S[nt][3]));
        }
        mx0 = fmaxf(mx0, __shfl_xor_sync(0xffffffffu, mx0, 1));
        mx0 = fmaxf(mx0, __shfl_xor_sync(0xffffffffu, mx0, 2));
        mx1 = fmaxf(mx1, __shfl_xor_sync(0xffffffffu, mx1, 1));
        mx1 = fmaxf(mx1, __shfl_xor_sync(0xffffffffu, mx1, 2));
        const float nm0 = fmaxf(m0, mx0), nm1 = fmaxf(m1, mx1);
        const float f0 = ex2f(m0 - nm0), f1 = ex2f(m1 - nm1);
        m0 = nm0; m1 = nm1;

        unsigned Ph[16][2];
        #pragma unroll
        for (int nt=0; nt<16; ++nt){
            Ph[nt][0] = hex2(packh2(S[nt][0] - nm0, S[nt][1] - nm0));
            Ph[nt][1] = hex2(packh2(S[nt][2] - nm1, S[nt][3] - nm1));
        }

        #pragma unroll
        for (int nt=0; nt<16; ++nt){
            O[nt][0] *= f0; O[nt][1] *= f0; O[nt][2] *= f1; O[nt][3] *= f1;
        }

        // O += P @ V ; row-sum l via ones-MMA (fp32 accum, consistent with PV)
        float Lacc[4] = {0.f, 0.f, 0.f, 0.f};
        #pragma unroll
        for (int kk=0; kk<8; ++kk){
            const unsigned a0 = Ph[2*kk][0],   a1 = Ph[2*kk][1];
            const unsigned a2 = Ph[2*kk+1][0], a3 = Ph[2*kk+1][1];
            mma16(Lacc, a0,a1,a2,a3, ONES, ONES);
            #pragma unroll
            for (int np=0; np<8; np+=2){
                unsigned v0[4], v1[4];
                const int row = kk*16 + ((lane>>3)&1)*8 + (lane&7);
                const int d0  = np*16 + ((lane>>4)<<3);
                ldsm4t(v0, bV + 2u*(unsigned)swh(row, d0));
                ldsm4t(v1, bV + 2u*(unsigned)swh(row, d0 + 16));
                mma16(O[2*np],   a0,a1,a2,a3, v0[0], v0[1]);
                mma16(O[2*np+1], a0,a1,a2,a3, v0[2], v0[3]);
                mma16(O[2*np+2], a0,a1,a2,a3, v1[0], v1[1]);
                mma16(O[2*np+3], a0,a1,a2,a3, v1[2], v1[3]);
            }
        }
        l0 = l0*f0 + Lacc[0];
        l1 = l1*f1 + Lacc[2];

        __syncthreads();          // all warps done with slot (j&1)
        issueKV(j+2);             // refill freed slot (empty commit past end)
    }

    // epilogue: normalize, write fp16 Y[b, t, h*128 + d]
    const float inv0 = 1.f / l0, inv1 = 1.f / l1;
    const int rg = qtile*128 + wrow + lr;
    const size_t base = ((size_t)(bh>>4)*SEQ + rg)*CDIM + (bh&15)*DK;
    #pragma unroll
    for (int nt=0; nt<16; ++nt){
        *(unsigned*)(Yg + base + nt*8 + 2*lk) = packh2(O[nt][0]*inv0, O[nt][1]*inv0);
        *(unsigned*)(Yg + base + (size_t)8*CDIM + nt*8 + 2*lk) = packh2(O[nt][2]*inv1, O[nt][3]*inv1);
    }
}

extern "C" void kernel_launch(void* const* d_in, const int* in_sizes, int n_in,
                              void* d_out, int out_size)
{
    const float* x      = (const float*)d_in[0];
    const float* w_attn = (const float*)d_in[1];
    const float* b_attn = (const float*)d_in[2];
    const float* w_proj = (const float*)d_in[3];
    const float* b_proj = (const float*)d_in[4];

    float* yOut = (float*)d_out;
    float* kOut = yOut + (size_t)BTC;
    float* vOut = yOut + (size_t)2*BTC;

    __half *Xh, *WAh, *WPh, *Qh, *Kh, *Vh, *Yh;
    cudaGetSymbolAddress((void**)&Xh,  g_Xh);
    cudaGetSymbolAddress((void**)&WAh, g_WAh);
    cudaGetSymbolAddress((void**)&WPh, g_WPh);
    cudaGetSymbolAddress((void**)&Qh,  g_Qh);
    cudaGetSymbolAddress((void**)&Kh,  g_Kh);
    cudaGetSymbolAddress((void**)&Vh,  g_Vh);
    cudaGetSymbolAddress((void**)&Yh,  g_Yh);

    const int smemG = 147456;   // 3 stages x 48KB
    const int smemF = 163840;   // Q 32K + K 2x32K + V 2x32K
    cudaFuncSetAttribute((const void*)gemm_h<0>, cudaFuncAttributeMaxDynamicSharedMemorySize, smemG);
    cudaFuncSetAttribute((const void*)gemm_h<1>, cudaFuncAttributeMaxDynamicSharedMemorySize, smemG);
    cudaFuncSetAttribute((const void*)flash_attn, cudaFuncAttributeMaxDynamicSharedMemorySize, smemF);

    // 0) fused one-time fp16 conversions (x | w_attn | w_proj)
    cvt_all<<<16384, 256>>>(x, w_attn, w_proj, Xh, WAh, WPh);

    // 1) QKV = x @ w_attn^T + b_attn  (M=8192, N=6144, K=2048), 256x128 tiles
    gemm_h<0><<<dim3(48,32), 512, smemG>>>(Xh, WAh, b_attn,
                                           nullptr, kOut, vOut, Qh, Kh, Vh);

    // 2) fused flash attention: Y = softmax(QK^T/sqrt(dk), causal) V  -> fp16 Yh
    flash_attn<<<dim3(64,16), 256, smemF>>>(Qh, Kh, Vh, Yh);

    // 3) y = Y @ w_proj^T + b_proj   (M=8192, N=2048, K=2048), 256x128 tiles
    gemm_h<1><<<dim3(16,32), 512, smemG>>>(Yh, WPh, b_proj,
                                           yOut, nullptr, nullptr, nullptr, nullptr, nullptr);
}

// round 12
// speedup vs baseline: 1.1016x; 1.1016x over previous
#include <cuda_runtime.h>
#include <cuda_fp16.h>
#include <cstdint>

#define BATCH 4
#define SEQ   2048
#define CDIM  2048
#define NH    16
#define DK    128
#define BH    (BATCH*NH)          /* 64  */
#define BTC   (BATCH*SEQ*CDIM)    /* 16777216 */

// Scratch (static device arrays: sanctioned scratch mechanism, no allocs)
__device__ __align__(16) __half g_Xh [(size_t)BTC];         // x fp16      (32 MB)
__device__ __align__(16) __half g_WAh[(size_t)3*CDIM*CDIM]; // w_attn fp16 (24 MB)
__device__ __align__(16) __half g_WPh[(size_t)CDIM*CDIM];   // w_proj fp16 ( 8 MB)
__device__ __align__(16) __half g_Qh [(size_t)BH*SEQ*DK];   // Q fp16 (pre-scaled) [b,h,t,d]
__device__ __align__(16) __half g_Kh [(size_t)BH*SEQ*DK];   // K fp16 [b,h,t,d]
__device__ __align__(16) __half g_Vh [(size_t)BH*SEQ*DK];   // V fp16 [b,h,t,d]
__device__ __align__(16) __half g_Yh [(size_t)BTC];         // attn out fp16 [b,t,c]

#define QSCALE 0.1275310112f      /* log2e / sqrt(128), folded into Q scratch */

__device__ __forceinline__ unsigned packh2(float lo, float hi){
    unsigned d; asm("cvt.rn.f16x2.f32 %0, %1, %2;" : "=r"(d) : "f"(hi), "f"(lo)); return d;
}
__device__ __forceinline__ unsigned hex2(unsigned x){
    unsigned y; asm("ex2.approx.f16x2 %0, %1;" : "=r"(y) : "r"(x)); return y;
}
__device__ __forceinline__ float ex2f(float x){
    float y; asm("ex2.approx.f32 %0, %1;" : "=f"(y) : "f"(x)); return y;
}
__device__ __forceinline__ void mma16(float* c, unsigned a0, unsigned a1, unsigned a2,
                                      unsigned a3, unsigned b0, unsigned b1){
    asm volatile("mma.sync.aligned.m16n8k16.row.col.f32.f16.f16.f32 "
        "{%0,%1,%2,%3}, {%4,%5,%6,%7}, {%8,%9}, {%0,%1,%2,%3};\n"
        : "+f"(c[0]), "+f"(c[1]), "+f"(c[2]), "+f"(c[3])
        : "r"(a0), "r"(a1), "r"(a2), "r"(a3), "r"(b0), "r"(b1));
}
__device__ __forceinline__ void ldsm4(unsigned* r, unsigned addr){
    asm volatile("ldmatrix.sync.aligned.m8n8.x4.shared.b16 {%0,%1,%2,%3}, [%4];"
        : "=r"(r[0]), "=r"(r[1]), "=r"(r[2]), "=r"(r[3]) : "r"(addr));
}
__device__ __forceinline__ void ldsm4t(unsigned* r, unsigned addr){
    asm volatile("ldmatrix.sync.aligned.m8n8.x4.trans.shared.b16 {%0,%1,%2,%3}, [%4];"
        : "=r"(r[0]), "=r"(r[1]), "=r"(r[2]), "=r"(r[3]) : "r"(addr));
}
__device__ __forceinline__ void cpa(unsigned dst, const void* src){
    asm volatile("cp.async.cg.shared.global [%0], [%1], 16;\n" :: "r"(dst), "l"(src));
}
__device__ __forceinline__ void cpcommit(){ asm volatile("cp.async.commit_group;\n"); }
template<int N> __device__ __forceinline__ void cpwait(){
    asm volatile("cp.async.wait_group %0;\n" :: "n"(N));
}
// half index into a [rows][128 halfs] fp16 tile (256B rows), 16B-group xor swizzle
__device__ __forceinline__ int swh(int r, int h){
    int g = h >> 3;
    return r*128 + (((g & 8) | ((g & 7) ^ (r & 7))) << 3) + (h & 7);
}

// ===================== fused fp32 -> fp16 conversion (x, w_attn, w_proj) ============
__global__ void __launch_bounds__(256)
cvt_all(const float* __restrict__ x, const float* __restrict__ wa,
        const float* __restrict__ wp,
        __half* __restrict__ xo, __half* __restrict__ wao, __half* __restrict__ wpo)
{
    const int b = blockIdx.x;
    const float* in; __half* out; size_t off;
    if (b < 8192)       { in = x;  out = xo;  off = (size_t)b*2048; }
    else if (b < 14336) { in = wa; out = wao; off = (size_t)(b-8192)*2048; }
    else                { in = wp; out = wpo; off = (size_t)(b-14336)*2048; }
    const size_t i = off + (size_t)threadIdx.x*8;
    float4 a = *(const float4*)(in + i);
    float4 c = *(const float4*)(in + i + 4);
    uint4 o = make_uint4(packh2(a.x,a.y), packh2(a.z,a.w), packh2(c.x,c.y), packh2(c.z,c.w));
    *(uint4*)(out + i) = o;
}

// ===================== fp16 GEMM: 128x128 tile, 3-stage cp.async, 2 CTA/SM ==========
// D = A[128rows,2048] @ B[128rows,2048]^T + bias. 8 warps as 4(m)x2(n), warp 32x64.
// A-fragments double-buffered across k16 steps (+8 regs, stays under the 128 cap).
// MODE 0: QKV -> Q fp16 (pre-scaled) / K fp32+fp16 / V fp32+fp16.  MODE 1: proj -> fp32.
template<int MODE>
__global__ void __launch_bounds__(256, 2)
gemm_h(const __half* __restrict__ Ag, const __half* __restrict__ Bg,
       const float* __restrict__ bias,
       float* __restrict__ F0, float* __restrict__ F1, float* __restrict__ F2,
       __half* __restrict__ H0, __half* __restrict__ H1, __half* __restrict__ H2)
{
    extern __shared__ __half sh[];   // 3 stages x (A 128x64 | B 128x64) = 96KB
    const unsigned sb = (unsigned)__cvta_generic_to_shared(sh);
    const int tid  = threadIdx.x;
    const int lane = tid & 31, w = tid >> 5;
    const int wm = w >> 1, wn = w & 1;
    const int lr = lane >> 2, lk = lane & 3;
    const int mBase = blockIdx.y*128, nBase = blockIdx.x*128;

    const __half* A = Ag + (size_t)mBase*2048;
    const __half* B = Bg + (size_t)nBase*2048;

    const int l15 = lane & 15;
    int aRow[2], bRow[4];
    #pragma unroll
    for (int mt=0; mt<2; ++mt) aRow[mt] = wm*32 + mt*16 + l15;
    #pragma unroll
    for (int np=0; np<4; ++np) bRow[np] = wn*64 + np*16 + ((lane>>4)<<3) + (lane&7);
    const int gA = lane >> 4, gB = (lane >> 3) & 1;

    float acc[2][8][4];
    #pragma unroll
    for (int mt=0; mt<2; ++mt)
      #pragma unroll
      for (int nt=0; nt<8; ++nt)
        #pragma unroll
        for (int i=0; i<4; ++i) acc[mt][nt][i] = 0.f;

    auto issue = [&](int slot, int kt){
        const unsigned st = sb + (unsigned)slot*32768u;
        #pragma unroll
        for (int i=0;i<4;++i){
            int idx = tid + i*256, r = idx>>3, g = idx&7;
            cpa(st + (unsigned)(r*128) + (unsigned)((g^(r&7))<<4),
                A + (size_t)r*2048 + kt*64 + g*8);
        }
        #pragma unroll
        for (int i=0;i<4;++i){
            int idx = tid + i*256, r = idx>>3, g = idx&7;
            cpa(st + 16384u + (unsigned)(r*128) + (unsigned)((g^(r&7))<<4),
                B + (size_t)r*2048 + kt*64 + g*8);
        }
    };

    issue(0,0); cpcommit();
    issue(1,1); cpcommit();

    const int KT = 32;
    for (int kt=0; kt<KT; ++kt){
        cpwait<1>();
        __syncthreads();
        const unsigned stA = sb + (unsigned)(kt%3)*32768u;
        const unsigned stB = stA + 16384u;

        unsigned afA[2][2][4];   // [buf][mt][4] A fragments, double-buffered over ks
        #pragma unroll
        for (int mt=0; mt<2; ++mt)
            ldsm4(afA[0][mt], stA + (unsigned)(aRow[mt]*128) + (unsigned)((gA^(aRow[mt]&7))<<4));

        #pragma unroll
        for (int ks=0; ks<4; ++ks){
            unsigned bf[4][4];
            #pragma unroll
            for (int np=0; np<4; ++np)
                ldsm4(bf[np], stB + (unsigned)(bRow[np]*128) + (unsigned)(((2*ks+gB)^(bRow[np]&7))<<4));
            if (ks < 3){
                #pragma unroll
                for (int mt=0; mt<2; ++mt)
                    ldsm4(afA[(ks+1)&1][mt],
                          stA + (unsigned)(aRow[mt]*128) + (unsigned)(((2*(ks+1)+gA)^(aRow[mt]&7))<<4));
            }
            const unsigned (*af)[4] = afA[ks&1];
            #pragma unroll
            for (int mt=0; mt<2; ++mt)
                #pragma unroll
                for (int nt=0; nt<8; ++nt)
                    mma16(acc[mt][nt], af[mt][0], af[mt][1], af[mt][2], af[mt][3],
                          bf[nt>>1][2*(nt&1)], bf[nt>>1][2*(nt&1)+1]);
        }
        if (kt+2 < KT) issue((kt+2)%3, kt+2);
        cpcommit();
    }

    // epilogue: paired stores (col, col+1 contiguous)
    #pragma unroll
    for (int mt=0; mt<2; ++mt)
      #pragma unroll
      for (int nt=0; nt<8; ++nt){
        const int row0 = mBase + wm*32 + mt*16 + lr;
        const int col  = nBase + wn*64 + nt*8 + 2*lk;
        float2 bv = *(const float2*)(bias + col);
        const float v00 = acc[mt][nt][0] + bv.x, v01 = acc[mt][nt][1] + bv.y;
        const float v10 = acc[mt][nt][2] + bv.x, v11 = acc[mt][nt][3] + bv.y;
        #pragma unroll
        for (int half=0; half<2; ++half){
            const int m = row0 + half*8;
            const float v0 = half ? v10 : v00, v1 = half ? v11 : v01;
            if (MODE == 0){
                const int bb = m >> 11, t = m & 2047;
                if (col < 2048){
                    const size_t idx = ((size_t)((bb*16 + (col>>7))*2048 + t))*128 + (col & 127);
                    *(unsigned*)(H0 + idx) = packh2(v0*QSCALE, v1*QSCALE);   // Q fp16 scaled
                } else if (col < 4096){
                    const int o = col - 2048;
                    const size_t idx = ((size_t)((bb*16 + (o>>7))*2048 + t))*128 + (o & 127);
                    *(float2*)(F1 + idx) = make_float2(v0, v1);              // K fp32 out
                    *(unsigned*)(H1 + idx) = packh2(v0, v1);                 // K fp16
                } else {
                    const int o = col - 4096;
                    const size_t idx = ((size_t)((bb*16 + (o>>7))*2048 + t))*128 + (o & 127);
                    *(float2*)(F2 + idx) = make_float2(v0, v1);              // V fp32 out
                    *(unsigned*)(H2 + idx) = packh2(v0, v1);                 // V fp16
                }
            } else {
                *(float2*)(F0 + (size_t)m*CDIM + col) = make_float2(v0, v1);
            }
        }
      }
}

// ===================== Fused flash attention (fp16 ops; f16x2 ex2; MMA row-sum) =====
// CTA = (q-tile 128 rows, bh). 8 warps; warp w owns q rows [16*rb(w), +16) where
// rb(w) = w<4 ? w : 11-w  — pairs {0,7},{1,6},{2,5},{3,4} per SMSP so the
// diagonal-tile skip (np<=wb in S, kk<=wb in PV) balances across schedulers.
// smem: sQ 32KB | sK[2] 32KB each | sV[2] 32KB each = 160KB. Double-buffered KV stream.
__global__ void __launch_bounds__(256, 1)
flash_attn(const __half* __restrict__ Qg_, const __half* __restrict__ Kg_,
           const __half* __restrict__ Vg_, __half* __restrict__ Yg)
{
    const int qtile = 15 - blockIdx.y;   // strict long-first launch order
    const int bh    = blockIdx.x;
    const int tid   = threadIdx.x;
    const int lane  = tid & 31, w = tid >> 5;
    const int lr    = lane >> 2, lk = lane & 3;
    const int wb    = (w < 4) ? w : 11 - w;   // row-block, SMSP-balanced for diagonal
    const int wrow  = wb * 16;
    const unsigned ONES = 0x3C003C00u;   // f16x2 (1.0, 1.0)

    extern __shared__ __half smh[];
    __half* sQh = smh;
    const unsigned sb  = (unsigned)__cvta_generic_to_shared(smh);
    const unsigned sbK = sb + 32768u;     // two 32KB K slots
    const unsigned sbV = sb + 98304u;     // two 32KB V slots

    const __half* Qg = Qg_ + (size_t)bh*SEQ*DK + (size_t)qtile*16384;
    const __half* Kg = Kg_ + (size_t)bh*SEQ*DK;
    const __half* Vg = Vg_ + (size_t)bh*SEQ*DK;

    auto issueKV = [&](int j){
        if (j <= qtile){
            const __half* Kj = Kg + (size_t)j*16384;
            const __half* Vj = Vg + (size_t)j*16384;
            const unsigned dK = sbK + (unsigned)(j&1)*32768u;
            const unsigned dV = sbV + (unsigned)(j&1)*32768u;
            #pragma unroll
            for (int i=0;i<8;++i){
                int idx = tid + i*256, r = idx>>4, g = idx&15;
                unsigned sw = (unsigned)((g&8)|((g&7)^(r&7)));
                cpa(dK + (unsigned)(r*256) + sw*16u, Kj + r*128 + g*8);
                cpa(dV + (unsigned)(r*256) + sw*16u, Vj + r*128 + g*8);
            }
        }
        cpcommit();
    };
    issueKV(0);
    issueKV(1);

    // stage Q (fp16 global -> swizzled smem)
    #pragma unroll
    for (int i=0;i<8;++i){
        int idx = tid + i*256, r = idx>>4, g = idx&15;
        int sw = (g&8)|((g&7)^(r&7));
        *(uint4*)&sQh[r*128 + sw*8] = *(const uint4*)(Qg + r*128 + g*8);
    }
    __syncthreads();

    // hoist Q fragments (reused across all kv tiles)
    unsigned qf[8][4];
    #pragma unroll
    for (int ks=0;ks<8;++ks){
        const int row = wrow + (lane & 15);
        const int h   = ks*16 + (lane>>4)*8;
        ldsm4(qf[ks], sb + 2u*(unsigned)swh(row, h));
    }

    float m0=-1e30f, m1=-1e30f, l0=0.f, l1=0.f;
    float O[16][4];
    #pragma unroll
    for (int nt=0; nt<16; ++nt){ O[nt][0]=0.f; O[nt][1]=0.f; O[nt][2]=0.f; O[nt][3]=0.f; }

    for (int j = 0; j <= qtile; ++j){
        cpwait<1>();
        __syncthreads();
        const unsigned bK = sbK + (unsigned)(j&1)*32768u;
        const unsigned bV = sbV + (unsigned)(j&1)*32768u;
        const bool diag = (j == qtile);

        // S = Q K^T  (Q pre-scaled; pairwise ldsm; diagonal: skip fully-masked blocks)
        float S[16][4];
        #pragma unroll
        for (int nt=0; nt<16; ++nt){ S[nt][0]=0.f; S[nt][1]=0.f; S[nt][2]=0.f; S[nt][3]=0.f; }
        #pragma unroll
        for (int ks=0; ks<8; ++ks){
            #pragma unroll
            for (int np=0; np<8; np+=2){
                if (diag && np > wb) continue;   // kv cols all > q rows: masked to 0 anyway
                unsigned k0[4], k1[4];
                const int row0 = np*16 + ((lane>>4)<<3) + (lane&7);
                const int h    = ks*16 + ((lane>>3)&1)*8;
                ldsm4(k0, bK + 2u*(unsigned)swh(row0,      h));
                ldsm4(k1, bK + 2u*(unsigned)swh(row0 + 16, h));
                mma16(S[2*np],   qf[ks][0],qf[ks][1],qf[ks][2],qf[ks][3], k0[0], k0[1]);
                mma16(S[2*np+1], qf[ks][0],qf[ks][1],qf[ks][2],qf[ks][3], k0[2], k0[3]);
                mma16(S[2*np+2], qf[ks][0],qf[ks][1],qf[ks][2],qf[ks][3], k1[0], k1[1]);
                mma16(S[2*np+3], qf[ks][0],qf[ks][1],qf[ks][2],qf[ks][3], k1[2], k1[3]);
            }
        }

        // causal mask on diagonal tile
        if (diag){
            #pragma unroll
            for (int nt=0; nt<16; ++nt){
                const int c0 = nt*8 + 2*lk, c1 = c0 + 1;
                const int r0 = wrow + lr,   r1 = r0 + 8;
                if (c0 > r0) S[nt][0] = -1e30f;
                if (c1 > r0) S[nt][1] = -1e30f;
                if (c0 > r1) S[nt][2] = -1e30f;
                if (c1 > r1) S[nt][3] = -1e30f;
            }
        }

        // online softmax: fp32 max-reduce, then f16x2 ex2 (P lands packed for PV)
        float mx0 = -1e30f, mx1 = -1e30f;
        #pragma unroll
        for (int nt=0; nt<16; ++nt){
            mx0 = fmaxf(mx0, fmaxf(S[nt][0], S[nt][1]));
            mx1 = fmaxf(mx1, fmaxf(S[nt][2], S[nt][3]));
        }
        mx0 = fmaxf(mx0, __shfl_xor_sync(0xffffffffu, mx0, 1));
        mx0 = fmaxf(mx0, __shfl_xor_sync(0xffffffffu, mx0, 2));
        mx1 = fmaxf(mx1, __shfl_xor_sync(0xffffffffu, mx1, 1));
        mx1 = fmaxf(mx1, __shfl_xor_sync(0xffffffffu, mx1, 2));
        const float nm0 = fmaxf(m0, mx0), nm1 = fmaxf(m1, mx1);
        const float f0 = ex2f(m0 - nm0), f1 = ex2f(m1 - nm1);
        m0 = nm0; m1 = nm1;

        unsigned Ph[16][2];
        #pragma unroll
        for (int nt=0; nt<16; ++nt){
            Ph[nt][0] = hex2(packh2(S[nt][0] - nm0, S[nt][1] - nm0));
            Ph[nt][1] = hex2(packh2(S[nt][2] - nm1, S[nt][3] - nm1));
        }

        #pragma unroll
        for (int nt=0; nt<16; ++nt){
            O[nt][0] *= f0; O[nt][1] *= f0; O[nt][2] *= f1; O[nt][3] *= f1;
        }

        // O += P @ V ; row-sum l via ones-MMA. Diagonal: skip kv-blocks with P==0.
        float Lacc[4] = {0.f, 0.f, 0.f, 0.f};
        #pragma unroll
        for (int kk=0; kk<8; ++kk){
            if (diag && kk > wb) continue;      // P exactly zero for kv rows > q rows
            const unsigned a0 = Ph[2*kk][0],   a1 = Ph[2*kk][1];
            const unsigned a2 = Ph[2*kk+1][0], a3 = Ph[2*kk+1][1];
            mma16(Lacc, a0,a1,a2,a3, ONES, ONES);
            #pragma unroll
            for (int np=0; np<8; np+=2){
                unsigned v0[4], v1[4];
                const int row = kk*16 + ((lane>>3)&1)*8 + (lane&7);
                const int d0  = np*16 + ((lane>>4)<<3);
                ldsm4t(v0, bV + 2u*(unsigned)swh(row, d0));
                ldsm4t(v1, bV + 2u*(unsigned)swh(row, d0 + 16));
                mma16(O[2*np],   a0,a1,a2,a3, v0[0], v0[1]);
                mma16(O[2*np+1], a0,a1,a2,a3, v0[2], v0[3]);
                mma16(O[2*np+2], a0,a1,a2,a3, v1[0], v1[1]);
                mma16(O[2*np+3], a0,a1,a2,a3, v1[2], v1[3]);
            }
        }
        l0 = l0*f0 + Lacc[0];
        l1 = l1*f1 + Lacc[2];

        __syncthreads();          // all warps done with slot (j&1)
        issueKV(j+2);             // refill freed slot (empty commit past end)
    }

    // epilogue: normalize, write fp16 Y[b, t, h*128 + d]
    const float inv0 = 1.f / l0, inv1 = 1.f / l1;
    const int rg = qtile*128 + wrow + lr;
    const size_t base = ((size_t)(bh>>4)*SEQ + rg)*CDIM + (bh&15)*DK;
    #pragma unroll
    for (int nt=0; nt<16; ++nt){
        *(unsigned*)(Yg + base + nt*8 + 2*lk) = packh2(O[nt][0]*inv0, O[nt][1]*inv0);
        *(unsigned*)(Yg + base + (size_t)8*CDIM + nt*8 + 2*lk) = packh2(O[nt][2]*inv1, O[nt][3]*inv1);
    }
}

extern "C" void kernel_launch(void* const* d_in, const int* in_sizes, int n_in,
                              void* d_out, int out_size)
{
    const float* x      = (const float*)d_in[0];
    const float* w_attn = (const float*)d_in[1];
    const float* b_attn = (const float*)d_in[2];
    const float* w_proj = (const float*)d_in[3];
    const float* b_proj = (const float*)d_in[4];

    float* yOut = (float*)d_out;
    float* kOut = yOut + (size_t)BTC;
    float* vOut = yOut + (size_t)2*BTC;

    __half *Xh, *WAh, *WPh, *Qh, *Kh, *Vh, *Yh;
    cudaGetSymbolAddress((void**)&Xh,  g_Xh);
    cudaGetSymbolAddress((void**)&WAh, g_WAh);
    cudaGetSymbolAddress((void**)&WPh, g_WPh);
    cudaGetSymbolAddress((void**)&Qh,  g_Qh);
    cudaGetSymbolAddress((void**)&Kh,  g_Kh);
    cudaGetSymbolAddress((void**)&Vh,  g_Vh);
    cudaGetSymbolAddress((void**)&Yh,  g_Yh);

    const int smemG = 98304;    // 3 stages x 32KB
    const int smemF = 163840;   // Q 32K + K 2x32K + V 2x32K
    cudaFuncSetAttribute((const void*)gemm_h<0>, cudaFuncAttributeMaxDynamicSharedMemorySize, smemG);
    cudaFuncSetAttribute((const void*)gemm_h<1>, cudaFuncAttributeMaxDynamicSharedMemorySize, smemG);
    cudaFuncSetAttribute((const void*)flash_attn, cudaFuncAttributeMaxDynamicSharedMemorySize, smemF);

    // 0) fused one-time fp16 conversions (x | w_attn | w_proj)
    cvt_all<<<16384, 256>>>(x, w_attn, w_proj, Xh, WAh, WPh);

    // 1) QKV = x @ w_attn^T + b_attn  (M=8192, N=6144, K=2048)
    gemm_h<0><<<dim3(48,64), 256, smemG>>>(Xh, WAh, b_attn,
                                           nullptr, kOut, vOut, Qh, Kh, Vh);

    // 2) fused flash attention: Y = softmax(QK^T/sqrt(dk), causal) V  -> fp16 Yh
    flash_attn<<<dim3(64,16), 256, smemF>>>(Qh, Kh, Vh, Yh);

    // 3) y = Y @ w_proj^T + b_proj   (M=8192, N=2048, K=2048)
    gemm_h<1><<<dim3(16,64), 256, smemG>>>(Yh, WPh, b_proj,
                                           yOut, nullptr, nullptr, nullptr, nullptr, nullptr);
}

// round 13
// speedup vs baseline: 1.1123x; 1.0097x over previous
#include <cuda_runtime.h>
#include <cuda_fp16.h>
#include <cstdint>

#define BATCH 4
#define SEQ   2048
#define CDIM  2048
#define NH    16
#define DK    128
#define BH    (BATCH*NH)          /* 64  */
#define BTC   (BATCH*SEQ*CDIM)    /* 16777216 */

// Scratch (static device arrays: sanctioned scratch mechanism, no allocs)
__device__ __align__(16) __half g_Xh [(size_t)BTC];         // x fp16      (32 MB)
__device__ __align__(16) __half g_WAh[(size_t)3*CDIM*CDIM]; // w_attn fp16 (24 MB)
__device__ __align__(16) __half g_WPh[(size_t)CDIM*CDIM];   // w_proj fp16 ( 8 MB)
__device__ __align__(16) __half g_Qh [(size_t)BH*SEQ*DK];   // Q fp16 (pre-scaled) [b,h,t,d]
__device__ __align__(16) __half g_Kh [(size_t)BH*SEQ*DK];   // K fp16 [b,h,t,d]
__device__ __align__(16) __half g_Vh [(size_t)BH*SEQ*DK];   // V fp16 [b,h,t,d]
__device__ __align__(16) __half g_Yh [(size_t)BTC];         // attn out fp16 [b,t,c]

#define QSCALE 0.1275310112f      /* log2e / sqrt(128), folded into Q scratch */

__device__ __forceinline__ unsigned packh2(float lo, float hi){
    unsigned d; asm("cvt.rn.f16x2.f32 %0, %1, %2;" : "=r"(d) : "f"(hi), "f"(lo)); return d;
}
__device__ __forceinline__ unsigned hex2(unsigned x){
    unsigned y; asm("ex2.approx.f16x2 %0, %1;" : "=r"(y) : "r"(x)); return y;
}
__device__ __forceinline__ float ex2f(float x){
    float y; asm("ex2.approx.f32 %0, %1;" : "=f"(y) : "f"(x)); return y;
}
__device__ __forceinline__ void mma16(float* c, unsigned a0, unsigned a1, unsigned a2,
                                      unsigned a3, unsigned b0, unsigned b1){
    asm volatile("mma.sync.aligned.m16n8k16.row.col.f32.f16.f16.f32 "
        "{%0,%1,%2,%3}, {%4,%5,%6,%7}, {%8,%9}, {%0,%1,%2,%3};\n"
        : "+f"(c[0]), "+f"(c[1]), "+f"(c[2]), "+f"(c[3])
        : "r"(a0), "r"(a1), "r"(a2), "r"(a3), "r"(b0), "r"(b1));
}
__device__ __forceinline__ void ldsm4(unsigned* r, unsigned addr){
    asm volatile("ldmatrix.sync.aligned.m8n8.x4.shared.b16 {%0,%1,%2,%3}, [%4];"
        : "=r"(r[0]), "=r"(r[1]), "=r"(r[2]), "=r"(r[3]) : "r"(addr));
}
__device__ __forceinline__ void ldsm4t(unsigned* r, unsigned addr){
    asm volatile("ldmatrix.sync.aligned.m8n8.x4.trans.shared.b16 {%0,%1,%2,%3}, [%4];"
        : "=r"(r[0]), "=r"(r[1]), "=r"(r[2]), "=r"(r[3]) : "r"(addr));
}
__device__ __forceinline__ void cpa(unsigned dst, const void* src){
    asm volatile("cp.async.cg.shared.global [%0], [%1], 16;\n" :: "r"(dst), "l"(src));
}
__device__ __forceinline__ void cpcommit(){ asm volatile("cp.async.commit_group;\n"); }
template<int N> __device__ __forceinline__ void cpwait(){
    asm volatile("cp.async.wait_group %0;\n" :: "n"(N));
}
// half index into a [rows][128 halfs] fp16 tile (256B rows), 16B-group xor swizzle
__device__ __forceinline__ int swh(int r, int h){
    int g = h >> 3;
    return r*128 + (((g & 8) | ((g & 7) ^ (r & 7))) << 3) + (h & 7);
}

// ===================== fused fp32 -> fp16 conversion (x, w_attn, w_proj) ============
__global__ void __launch_bounds__(256)
cvt_all(const float* __restrict__ x, const float* __restrict__ wa,
        const float* __restrict__ wp,
        __half* __restrict__ xo, __half* __restrict__ wao, __half* __restrict__ wpo)
{
    const int b = blockIdx.x;
    const float* in; __half* out; size_t off;
    if (b < 8192)       { in = x;  out = xo;  off = (size_t)b*2048; }
    else if (b < 14336) { in = wa; out = wao; off = (size_t)(b-8192)*2048; }
    else                { in = wp; out = wpo; off = (size_t)(b-14336)*2048; }
    const size_t i = off + (size_t)threadIdx.x*8;
    float4 a = *(const float4*)(in + i);
    float4 c = *(const float4*)(in + i + 4);
    uint4 o = make_uint4(packh2(a.x,a.y), packh2(a.z,a.w), packh2(c.x,c.y), packh2(c.z,c.w));
    *(uint4*)(out + i) = o;
}

// ===================== fp16 GEMM: 128x128 tile, 128 thr (4 warps 64x64), 2 CTA/SM ===
// D = A[128rows,2048] @ B[128rows,2048]^T + bias. Warp grid 2(m)x2(n), warp 64x64.
// MMA/LDSM = 5.33 (vs 2.67 at 32x64 warps): MIO ceiling ~100% of tensor pipe.
// 3-stage cp.async, 96KB smem, 2 independent CTAs/SM (regs ~190 < 256 cap).
// MODE 0: QKV -> Q fp16 (pre-scaled) / K fp32+fp16 / V fp32+fp16.  MODE 1: proj -> fp32.
template<int MODE>
__global__ void __launch_bounds__(128, 2)
gemm_h(const __half* __restrict__ Ag, const __half* __restrict__ Bg,
       const float* __restrict__ bias,
       float* __restrict__ F0, float* __restrict__ F1, float* __restrict__ F2,
       __half* __restrict__ H0, __half* __restrict__ H1, __half* __restrict__ H2)
{
    extern __shared__ __half sh[];   // 3 stages x (A 128x64 | B 128x64) = 96KB
    const unsigned sb = (unsigned)__cvta_generic_to_shared(sh);
    const int tid  = threadIdx.x;
    const int lane = tid & 31, w = tid >> 5;
    const int wm = w >> 1, wn = w & 1;            // 2(m) x 2(n)
    const int lr = lane >> 2, lk = lane & 3;
    const int mBase = blockIdx.y*128, nBase = blockIdx.x*128;

    const __half* A = Ag + (size_t)mBase*2048;
    const __half* B = Bg + (size_t)nBase*2048;

    const int l15 = lane & 15;
    int aRow[4], bRow[4];
    #pragma unroll
    for (int mt=0; mt<4; ++mt) aRow[mt] = wm*64 + mt*16 + l15;
    #pragma unroll
    for (int np=0; np<4; ++np) bRow[np] = wn*64 + np*16 + ((lane>>4)<<3) + (lane&7);
    const int gA = lane >> 4, gB = (lane >> 3) & 1;

    float acc[4][8][4];
    #pragma unroll
    for (int mt=0; mt<4; ++mt)
      #pragma unroll
      for (int nt=0; nt<8; ++nt)
        #pragma unroll
        for (int i=0; i<4; ++i) acc[mt][nt][i] = 0.f;

    auto issue = [&](int slot, int kt){
        const unsigned st = sb + (unsigned)slot*32768u;
        #pragma unroll
        for (int i=0;i<8;++i){
            int idx = tid + i*128, r = idx>>3, g = idx&7;
            cpa(st + (unsigned)(r*128) + (unsigned)((g^(r&7))<<4),
                A + (size_t)r*2048 + kt*64 + g*8);
        }
        #pragma unroll
        for (int i=0;i<8;++i){
            int idx = tid + i*128, r = idx>>3, g = idx&7;
            cpa(st + 16384u + (unsigned)(r*128) + (unsigned)((g^(r&7))<<4),
                B + (size_t)r*2048 + kt*64 + g*8);
        }
    };

    issue(0,0); cpcommit();
    issue(1,1); cpcommit();

    const int KT = 32;
    for (int kt=0; kt<KT; ++kt){
        cpwait<1>();
        __syncthreads();
        const unsigned stA = sb + (unsigned)(kt%3)*32768u;
        const unsigned stB = stA + 16384u;

        #pragma unroll
        for (int ks=0; ks<4; ++ks){
            unsigned af[4][4], bf[4][4];
            #pragma unroll
            for (int mt=0; mt<4; ++mt)
                ldsm4(af[mt], stA + (unsigned)(aRow[mt]*128) + (unsigned)(((2*ks+gA)^(aRow[mt]&7))<<4));
            #pragma unroll
            for (int np=0; np<4; ++np)
                ldsm4(bf[np], stB + (unsigned)(bRow[np]*128) + (unsigned)(((2*ks+gB)^(bRow[np]&7))<<4));
            #pragma unroll
            for (int mt=0; mt<4; ++mt)
                #pragma unroll
                for (int nt=0; nt<8; ++nt)
                    mma16(acc[mt][nt], af[mt][0], af[mt][1], af[mt][2], af[mt][3],
                          bf[nt>>1][2*(nt&1)], bf[nt>>1][2*(nt&1)+1]);
        }
        if (kt+2 < KT) issue((kt+2)%3, kt+2);
        cpcommit();
    }

    // epilogue: paired stores (col, col+1 contiguous)
    #pragma unroll
    for (int mt=0; mt<4; ++mt)
      #pragma unroll
      for (int nt=0; nt<8; ++nt){
        const int row0 = mBase + wm*64 + mt*16 + lr;
        const int col  = nBase + wn*64 + nt*8 + 2*lk;
        float2 bv = *(const float2*)(bias + col);
        const float v00 = acc[mt][nt][0] + bv.x, v01 = acc[mt][nt][1] + bv.y;
        const float v10 = acc[mt][nt][2] + bv.x, v11 = acc[mt][nt][3] + bv.y;
        #pragma unroll
        for (int half=0; half<2; ++half){
            const int m = row0 + half*8;
            const float v0 = half ? v10 : v00, v1 = half ? v11 : v01;
            if (MODE == 0){
                const int bb = m >> 11, t = m & 2047;
                if (col < 2048){
                    const size_t idx = ((size_t)((bb*16 + (col>>7))*2048 + t))*128 + (col & 127);
                    *(unsigned*)(H0 + idx) = packh2(v0*QSCALE, v1*QSCALE);   // Q fp16 scaled
                } else if (col < 4096){
                    const int o = col - 2048;
                    const size_t idx = ((size_t)((bb*16 + (o>>7))*2048 + t))*128 + (o & 127);
                    *(float2*)(F1 + idx) = make_float2(v0, v1);              // K fp32 out
                    *(unsigned*)(H1 + idx) = packh2(v0, v1);                 // K fp16
                } else {
                    const int o = col - 4096;
                    const size_t idx = ((size_t)((bb*16 + (o>>7))*2048 + t))*128 + (o & 127);
                    *(float2*)(F2 + idx) = make_float2(v0, v1);              // V fp32 out
                    *(unsigned*)(H2 + idx) = packh2(v0, v1);                 // V fp16
                }
            } else {
                *(float2*)(F0 + (size_t)m*CDIM + col) = make_float2(v0, v1);
            }
        }
      }
}

// ===================== Fused flash attention (fp16 ops; f16x2 ex2; MMA row-sum) =====
// CTA = (q-tile 128 rows, bh). 8 warps; warp w owns q rows [16w,16w+16).
// smem: sQ 32KB | sK[2] 32KB each | sV[2] 32KB each = 160KB. Double-buffered KV stream.
__global__ void __launch_bounds__(256, 1)
flash_attn(const __half* __restrict__ Qg_, const __half* __restrict__ Kg_,
           const __half* __restrict__ Vg_, __half* __restrict__ Yg)
{
    const int qtile = 15 - blockIdx.y;   // strict long-first launch order
    const int bh    = blockIdx.x;
    const int tid   = threadIdx.x;
    const int lane  = tid & 31, w = tid >> 5;
    const int lr    = lane >> 2, lk = lane & 3;
    const int wrow  = w * 16;
    const unsigned ONES = 0x3C003C00u;   // f16x2 (1.0, 1.0)

    extern __shared__ __half smh[];
    __half* sQh = smh;
    const unsigned sb  = (unsigned)__cvta_generic_to_shared(smh);
    const unsigned sbK = sb + 32768u;     // two 32KB K slots
    const unsigned sbV = sb + 98304u;     // two 32KB V slots

    const __half* Qg = Qg_ + (size_t)bh*SEQ*DK + (size_t)qtile*16384;
    const __half* Kg = Kg_ + (size_t)bh*SEQ*DK;
    const __half* Vg = Vg_ + (size_t)bh*SEQ*DK;

    auto issueKV = [&](int j){
        if (j <= qtile){
            const __half* Kj = Kg + (size_t)j*16384;
            const __half* Vj = Vg + (size_t)j*16384;
            const unsigned dK = sbK + (unsigned)(j&1)*32768u;
            const unsigned dV = sbV + (unsigned)(j&1)*32768u;
            #pragma unroll
            for (int i=0;i<8;++i){
                int idx = tid + i*256, r = idx>>4, g = idx&15;
                unsigned sw = (unsigned)((g&8)|((g&7)^(r&7)));
                cpa(dK + (unsigned)(r*256) + sw*16u, Kj + r*128 + g*8);
                cpa(dV + (unsigned)(r*256) + sw*16u, Vj + r*128 + g*8);
            }
        }
        cpcommit();
    };
    issueKV(0);
    issueKV(1);

    // stage Q (fp16 global -> swizzled smem)
    #pragma unroll
    for (int i=0;i<8;++i){
        int idx = tid + i*256, r = idx>>4, g = idx&15;
        int sw = (g&8)|((g&7)^(r&7));
        *(uint4*)&sQh[r*128 + sw*8] = *(const uint4*)(Qg + r*128 + g*8);
    }
    __syncthreads();

    // hoist Q fragments (reused across all kv tiles)
    unsigned qf[8][4];
    #pragma unroll
    for (int ks=0;ks<8;++ks){
        const int row = wrow + (lane & 15);
        const int h   = ks*16 + (lane>>4)*8;
        ldsm4(qf[ks], sb + 2u*(unsigned)swh(row, h));
    }

    float m0=-1e30f, m1=-1e30f, l0=0.f, l1=0.f;
    float O[16][4];
    #pragma unroll
    for (int nt=0; nt<16; ++nt){ O[nt][0]=0.f; O[nt][1]=0.f; O[nt][2]=0.f; O[nt][3]=0.f; }

    for (int j = 0; j <= qtile; ++j){
        cpwait<1>();
        __syncthreads();
        const unsigned bK = sbK + (unsigned)(j&1)*32768u;
        const unsigned bV = sbV + (unsigned)(j&1)*32768u;

        // S = Q K^T  (Q pre-scaled by log2e/sqrt(dk); pairwise ldsm)
        float S[16][4];
        #pragma unroll
        for (int nt=0; nt<16; ++nt){ S[nt][0]=0.f; S[nt][1]=0.f; S[nt][2]=0.f; S[nt][3]=0.f; }
        #pragma unroll
        for (int ks=0; ks<8; ++ks){
            #pragma unroll
            for (int np=0; np<8; np+=2){
                unsigned k0[4], k1[4];
                const int row0 = np*16 + ((lane>>4)<<3) + (lane&7);
                const int h    = ks*16 + ((lane>>3)&1)*8;
                ldsm4(k0, bK + 2u*(unsigned)swh(row0,      h));
                ldsm4(k1, bK + 2u*(unsigned)swh(row0 + 16, h));
                mma16(S[2*np],   qf[ks][0],qf[ks][1],qf[ks][2],qf[ks][3], k0[0], k0[1]);
                mma16(S[2*np+1], qf[ks][0],qf[ks][1],qf[ks][2],qf[ks][3], k0[2], k0[3]);
                mma16(S[2*np+2], qf[ks][0],qf[ks][1],qf[ks][2],qf[ks][3], k1[0], k1[1]);
                mma16(S[2*np+3], qf[ks][0],qf[ks][1],qf[ks][2],qf[ks][3], k1[2], k1[3]);
            }
        }

        // causal mask on diagonal tile
        if (j == qtile){
            #pragma unroll
            for (int nt=0; nt<16; ++nt){
                const int c0 = nt*8 + 2*lk, c1 = c0 + 1;
                const int r0 = wrow + lr,   r1 = r0 + 8;
                if (c0 > r0) S[nt][0] = -1e30f;
                if (c1 > r0) S[nt][1] = -1e30f;
                if (c0 > r1) S[nt][2] = -1e30f;
                if (c1 > r1) S[nt][3] = -1e30f;
            }
        }

        // online softmax: fp32 max-reduce, then f16x2 ex2 (P lands packed for PV)
        float mx0 = -1e30f, mx1 = -1e30f;
        #pragma unroll
        for (int nt=0; nt<16; ++nt){
            mx0 = fmaxf(mx0, fmaxf(S[nt][0], S[nt][1]));
            mx1 = fmaxf(mx1, fmaxf(S[nt][2], S[nt][3]));
        }
        mx0 = fmaxf(mx0, __shfl_xor_sync(0xffffffffu, mx0, 1));
        mx0 = fmaxf(mx0, __shfl_xor_sync(0xffffffffu, mx0, 2));
        mx1 = fmaxf(mx1, __shfl_xor_sync(0xffffffffu, mx1, 1));
        mx1 = fmaxf(mx1, __shfl_xor_sync(0xffffffffu, mx1, 2));
        const float nm0 = fmaxf(m0, mx0), nm1 = fmaxf(m1, mx1);
        const float f0 = ex2f(m0 - nm0), f1 = ex2f(m1 - nm1);
        m0 = nm0; m1 = nm1;

        unsigned Ph[16][2];
        #pragma unroll
        for (int nt=0; nt<16; ++nt){
            Ph[nt][0] = hex2(packh2(S[nt][0] - nm0, S[nt][1] - nm0));
            Ph[nt][1] = hex2(packh2(S[nt][2] - nm1, S[nt][3] - nm1));
        }

        #pragma unroll
        for (int nt=0; nt<16; ++nt){
            O[nt][0] *= f0; O[nt][1] *= f0; O[nt][2] *= f1; O[nt][3] *= f1;
        }

        // O += P @ V ; row-sum l via ones-MMA (fp32 accum, consistent with PV)
        float Lacc[4] = {0.f, 0.f, 0.f, 0.f};
        #pragma unroll
        for (int kk=0; kk<8; ++kk){
            const unsigned a0 = Ph[2*kk][0],   a1 = Ph[2*kk][1];
            const unsigned a2 = Ph[2*kk+1][0], a3 = Ph[2*kk+1][1];
            mma16(Lacc, a0,a1,a2,a3, ONES, ONES);
            #pragma unroll
            for (int np=0; np<8; np+=2){
                unsigned v0[4], v1[4];
                const int row = kk*16 + ((lane>>3)&1)*8 + (lane&7);
                const int d0  = np*16 + ((lane>>4)<<3);
                ldsm4t(v0, bV + 2u*(unsigned)swh(row, d0));
                ldsm4t(v1, bV + 2u*(unsigned)swh(row, d0 + 16));
                mma16(O[2*np],   a0,a1,a2,a3, v0[0], v0[1]);
                mma16(O[2*np+1], a0,a1,a2,a3, v0[2], v0[3]);
                mma16(O[2*np+2], a0,a1,a2,a3, v1[0], v1[1]);
                mma16(O[2*np+3], a0,a1,a2,a3, v1[2], v1[3]);
            }
        }
        l0 = l0*f0 + Lacc[0];
        l1 = l1*f1 + Lacc[2];

        __syncthreads();          // all warps done with slot (j&1)
        issueKV(j+2);             // refill freed slot (empty commit past end)
    }

    // epilogue: normalize, write fp16 Y[b, t, h*128 + d]
    const float inv0 = 1.f / l0, inv1 = 1.f / l1;
    const int rg = qtile*128 + wrow + lr;
    const size_t base = ((size_t)(bh>>4)*SEQ + rg)*CDIM + (bh&15)*DK;
    #pragma unroll
    for (int nt=0; nt<16; ++nt){
        *(unsigned*)(Yg + base + nt*8 + 2*lk) = packh2(O[nt][0]*inv0, O[nt][1]*inv0);
        *(unsigned*)(Yg + base + (size_t)8*CDIM + nt*8 + 2*lk) = packh2(O[nt][2]*inv1, O[nt][3]*inv1);
    }
}

extern "C" void kernel_launch(void* const* d_in, const int* in_sizes, int n_in,
                              void* d_out, int out_size)
{
    const float* x      = (const float*)d_in[0];
    const float* w_attn = (const float*)d_in[1];
    const float* b_attn = (const float*)d_in[2];
    const float* w_proj = (const float*)d_in[3];
    const float* b_proj = (const float*)d_in[4];

    float* yOut = (float*)d_out;
    float* kOut = yOut + (size_t)BTC;
    float* vOut = yOut + (size_t)2*BTC;

    __half *Xh, *WAh, *WPh, *Qh, *Kh, *Vh, *Yh;
    cudaGetSymbolAddress((void**)&Xh,  g_Xh);
    cudaGetSymbolAddress((void**)&WAh, g_WAh);
    cudaGetSymbolAddress((void**)&WPh, g_WPh);
    cudaGetSymbolAddress((void**)&Qh,  g_Qh);
    cudaGetSymbolAddress((void**)&Kh,  g_Kh);
    cudaGetSymbolAddress((void**)&Vh,  g_Vh);
    cudaGetSymbolAddress((void**)&Yh,  g_Yh);

    const int smemG = 98304;    // 3 stages x 32KB
    const int smemF = 163840;   // Q 32K + K 2x32K + V 2x32K
    cudaFuncSetAttribute((const void*)gemm_h<0>, cudaFuncAttributeMaxDynamicSharedMemorySize, smemG);
    cudaFuncSetAttribute((const void*)gemm_h<1>, cudaFuncAttributeMaxDynamicSharedMemorySize, smemG);
    cudaFuncSetAttribute((const void*)flash_attn, cudaFuncAttributeMaxDynamicSharedMemorySize, smemF);

    // 0) fused one-time fp16 conversions (x | w_attn | w_proj)
    cvt_all<<<16384, 256>>>(x, w_attn, w_proj, Xh, WAh, WPh);

    // 1) QKV = x @ w_attn^T + b_attn  (M=8192, N=6144, K=2048), 4-warp CTAs
    gemm_h<0><<<dim3(48,64), 128, smemG>>>(Xh, WAh, b_attn,
                                           nullptr, kOut, vOut, Qh, Kh, Vh);

    // 2) fused flash attention: Y = softmax(QK^T/sqrt(dk), causal) V  -> fp16 Yh
    flash_attn<<<dim3(64,16), 256, smemF>>>(Qh, Kh, Vh, Yh);

    // 3) y = Y @ w_proj^T + b_proj   (M=8192, N=2048, K=2048), 4-warp CTAs
    gemm_h<1><<<dim3(16,64), 128, smemG>>>(Yh, WPh, b_proj,
                                           yOut, nullptr, nullptr, nullptr, nullptr, nullptr);
}

// round 14
// speedup vs baseline: 1.1299x; 1.0158x over previous
#include <cuda_runtime.h>
#include <cuda_fp16.h>
#include <cstdint>

#define BATCH 4
#define SEQ   2048
#define CDIM  2048
#define NH    16
#define DK    128
#define BH    (BATCH*NH)          /* 64  */
#define BTC   (BATCH*SEQ*CDIM)    /* 16777216 */

// Scratch (static device arrays: sanctioned scratch mechanism, no allocs)
__device__ __align__(16) __half g_Xh [(size_t)BTC];         // x fp16      (32 MB)
__device__ __align__(16) __half g_WAh[(size_t)3*CDIM*CDIM]; // w_attn fp16 (24 MB)
__device__ __align__(16) __half g_WPh[(size_t)CDIM*CDIM];   // w_proj fp16 ( 8 MB)
__device__ __align__(16) __half g_Qh [(size_t)BH*SEQ*DK];   // Q fp16 (pre-scaled) [b,h,t,d]
__device__ __align__(16) __half g_Kh [(size_t)BH*SEQ*DK];   // K fp16 [b,h,t,d]
__device__ __align__(16) __half g_Vh [(size_t)BH*SEQ*DK];   // V fp16 [b,h,t,d]
__device__ __align__(16) __half g_Yh [(size_t)BTC];         // attn out fp16 [b,t,c]

#define QSCALE 0.1275310112f      /* log2e / sqrt(128), folded into Q scratch */

__device__ __forceinline__ unsigned packh2(float lo, float hi){
    unsigned d; asm("cvt.rn.f16x2.f32 %0, %1, %2;" : "=r"(d) : "f"(hi), "f"(lo)); return d;
}
__device__ __forceinline__ unsigned hex2(unsigned x){
    unsigned y; asm("ex2.approx.f16x2 %0, %1;" : "=r"(y) : "r"(x)); return y;
}
__device__ __forceinline__ float ex2f(float x){
    float y; asm("ex2.approx.f32 %0, %1;" : "=f"(y) : "f"(x)); return y;
}
__device__ __forceinline__ void mma16(float* c, unsigned a0, unsigned a1, unsigned a2,
                                      unsigned a3, unsigned b0, unsigned b1){
    asm volatile("mma.sync.aligned.m16n8k16.row.col.f32.f16.f16.f32 "
        "{%0,%1,%2,%3}, {%4,%5,%6,%7}, {%8,%9}, {%0,%1,%2,%3};\n"
        : "+f"(c[0]), "+f"(c[1]), "+f"(c[2]), "+f"(c[3])
        : "r"(a0), "r"(a1), "r"(a2), "r"(a3), "r"(b0), "r"(b1));
}
__device__ __forceinline__ void ldsm4(unsigned* r, unsigned addr){
    asm volatile("ldmatrix.sync.aligned.m8n8.x4.shared.b16 {%0,%1,%2,%3}, [%4];"
        : "=r"(r[0]), "=r"(r[1]), "=r"(r[2]), "=r"(r[3]) : "r"(addr));
}
__device__ __forceinline__ void ldsm4t(unsigned* r, unsigned addr){
    asm volatile("ldmatrix.sync.aligned.m8n8.x4.trans.shared.b16 {%0,%1,%2,%3}, [%4];"
        : "=r"(r[0]), "=r"(r[1]), "=r"(r[2]), "=r"(r[3]) : "r"(addr));
}
__device__ __forceinline__ void cpa(unsigned dst, const void* src){
    asm volatile("cp.async.cg.shared.global [%0], [%1], 16;\n" :: "r"(dst), "l"(src));
}
__device__ __forceinline__ void cpcommit(){ asm volatile("cp.async.commit_group;\n"); }
template<int N> __device__ __forceinline__ void cpwait(){
    asm volatile("cp.async.wait_group %0;\n" :: "n"(N));
}
// half index into a [rows][128 halfs] fp16 tile (256B rows), 16B-group xor swizzle
__device__ __forceinline__ int swh(int r, int h){
    int g = h >> 3;
    return r*128 + (((g & 8) | ((g & 7) ^ (r & 7))) << 3) + (h & 7);
}

// ===================== fused fp32 -> fp16 conversion (x, w_attn, w_proj) ============
__global__ void __launch_bounds__(256)
cvt_all(const float* __restrict__ x, const float* __restrict__ wa,
        const float* __restrict__ wp,
        __half* __restrict__ xo, __half* __restrict__ wao, __half* __restrict__ wpo)
{
    const int b = blockIdx.x;
    const float* in; __half* out; size_t off;
    if (b < 8192)       { in = x;  out = xo;  off = (size_t)b*2048; }
    else if (b < 14336) { in = wa; out = wao; off = (size_t)(b-8192)*2048; }
    else                { in = wp; out = wpo; off = (size_t)(b-14336)*2048; }
    const size_t i = off + (size_t)threadIdx.x*8;
    float4 a = *(const float4*)(in + i);
    float4 c = *(const float4*)(in + i + 4);
    uint4 o = make_uint4(packh2(a.x,a.y), packh2(a.z,a.w), packh2(c.x,c.y), packh2(c.z,c.w));
    *(uint4*)(out + i) = o;
}

// ===================== fp16 GEMM: 128x128 tile, 128 thr (4 warps 64x64), 2 CTA/SM ===
// (R13 winner — unchanged)
template<int MODE>
__global__ void __launch_bounds__(128, 2)
gemm_h(const __half* __restrict__ Ag, const __half* __restrict__ Bg,
       const float* __restrict__ bias,
       float* __restrict__ F0, float* __restrict__ F1, float* __restrict__ F2,
       __half* __restrict__ H0, __half* __restrict__ H1, __half* __restrict__ H2)
{
    extern __shared__ __half sh[];   // 3 stages x (A 128x64 | B 128x64) = 96KB
    const unsigned sb = (unsigned)__cvta_generic_to_shared(sh);
    const int tid  = threadIdx.x;
    const int lane = tid & 31, w = tid >> 5;
    const int wm = w >> 1, wn = w & 1;            // 2(m) x 2(n)
    const int lr = lane >> 2, lk = lane & 3;
    const int mBase = blockIdx.y*128, nBase = blockIdx.x*128;

    const __half* A = Ag + (size_t)mBase*2048;
    const __half* B = Bg + (size_t)nBase*2048;

    const int l15 = lane & 15;
    int aRow[4], bRow[4];
    #pragma unroll
    for (int mt=0; mt<4; ++mt) aRow[mt] = wm*64 + mt*16 + l15;
    #pragma unroll
    for (int np=0; np<4; ++np) bRow[np] = wn*64 + np*16 + ((lane>>4)<<3) + (lane&7);
    const int gA = lane >> 4, gB = (lane >> 3) & 1;

    float acc[4][8][4];
    #pragma unroll
    for (int mt=0; mt<4; ++mt)
      #pragma unroll
      for (int nt=0; nt<8; ++nt)
        #pragma unroll
        for (int i=0; i<4; ++i) acc[mt][nt][i] = 0.f;

    auto issue = [&](int slot, int kt){
        const unsigned st = sb + (unsigned)slot*32768u;
        #pragma unroll
        for (int i=0;i<8;++i){
            int idx = tid + i*128, r = idx>>3, g = idx&7;
            cpa(st + (unsigned)(r*128) + (unsigned)((g^(r&7))<<4),
                A + (size_t)r*2048 + kt*64 + g*8);
        }
        #pragma unroll
        for (int i=0;i<8;++i){
            int idx = tid + i*128, r = idx>>3, g = idx&7;
            cpa(st + 16384u + (unsigned)(r*128) + (unsigned)((g^(r&7))<<4),
                B + (size_t)r*2048 + kt*64 + g*8);
        }
    };

    issue(0,0); cpcommit();
    issue(1,1); cpcommit();

    const int KT = 32;
    for (int kt=0; kt<KT; ++kt){
        cpwait<1>();
        __syncthreads();
        const unsigned stA = sb + (unsigned)(kt%3)*32768u;
        const unsigned stB = stA + 16384u;

        #pragma unroll
        for (int ks=0; ks<4; ++ks){
            unsigned af[4][4], bf[4][4];
            #pragma unroll
            for (int mt=0; mt<4; ++mt)
                ldsm4(af[mt], stA + (unsigned)(aRow[mt]*128) + (unsigned)(((2*ks+gA)^(aRow[mt]&7))<<4));
            #pragma unroll
            for (int np=0; np<4; ++np)
                ldsm4(bf[np], stB + (unsigned)(bRow[np]*128) + (unsigned)(((2*ks+gB)^(bRow[np]&7))<<4));
            #pragma unroll
            for (int mt=0; mt<4; ++mt)
                #pragma unroll
                for (int nt=0; nt<8; ++nt)
                    mma16(acc[mt][nt], af[mt][0], af[mt][1], af[mt][2], af[mt][3],
                          bf[nt>>1][2*(nt&1)], bf[nt>>1][2*(nt&1)+1]);
        }
        if (kt+2 < KT) issue((kt+2)%3, kt+2);
        cpcommit();
    }

    // epilogue: paired stores (col, col+1 contiguous)
    #pragma unroll
    for (int mt=0; mt<4; ++mt)
      #pragma unroll
      for (int nt=0; nt<8; ++nt){
        const int row0 = mBase + wm*64 + mt*16 + lr;
        const int col  = nBase + wn*64 + nt*8 + 2*lk;
        float2 bv = *(const float2*)(bias + col);
        const float v00 = acc[mt][nt][0] + bv.x, v01 = acc[mt][nt][1] + bv.y;
        const float v10 = acc[mt][nt][2] + bv.x, v11 = acc[mt][nt][3] + bv.y;
        #pragma unroll
        for (int half=0; half<2; ++half){
            const int m = row0 + half*8;
            const float v0 = half ? v10 : v00, v1 = half ? v11 : v01;
            if (MODE == 0){
                const int bb = m >> 11, t = m & 2047;
                if (col < 2048){
                    const size_t idx = ((size_t)((bb*16 + (col>>7))*2048 + t))*128 + (col & 127);
                    *(unsigned*)(H0 + idx) = packh2(v0*QSCALE, v1*QSCALE);   // Q fp16 scaled
                } else if (col < 4096){
                    const int o = col - 2048;
                    const size_t idx = ((size_t)((bb*16 + (o>>7))*2048 + t))*128 + (o & 127);
                    *(float2*)(F1 + idx) = make_float2(v0, v1);              // K fp32 out
                    *(unsigned*)(H1 + idx) = packh2(v0, v1);                 // K fp16
                } else {
                    const int o = col - 4096;
                    const size_t idx = ((size_t)((bb*16 + (o>>7))*2048 + t))*128 + (o & 127);
                    *(float2*)(F2 + idx) = make_float2(v0, v1);              // V fp32 out
                    *(unsigned*)(H2 + idx) = packh2(v0, v1);                 // V fp16
                }
            } else {
                *(float2*)(F0 + (size_t)m*CDIM + col) = make_float2(v0, v1);
            }
        }
      }
}

// ===================== Fused flash attention: 64-row q-tiles, 128 thr, 2 CTA/SM =====
// CTA = (q-tile 64 rows, bh). 4 warps; warp w owns q rows [16w,16w+16).
// KV streamed in 64-row tiles, double-buffered. smem: Q 16K + K 2x16K + V 2x16K = 80KB.
// Two independent CTAs per SM: one CTA's softmax overlaps the other's MMAs.
__global__ void __launch_bounds__(128, 2)
flash_attn(const __half* __restrict__ Qg_, const __half* __restrict__ Kg_,
           const __half* __restrict__ Vg_, __half* __restrict__ Yg)
{
    const int qt  = 31 - blockIdx.y;     // strict long-first launch order (64-row tiles)
    const int bh  = blockIdx.x;
    const int tid = threadIdx.x;
    const int lane = tid & 31, w = tid >> 5;
    const int lr = lane >> 2, lk = lane & 3;
    const int wrow = w * 16;
    const unsigned ONES = 0x3C003C00u;   // f16x2 (1.0, 1.0)

    extern __shared__ __half smh[];
    __half* sQh = smh;                   // 64 x 128 halfs = 16KB
    const unsigned sb  = (unsigned)__cvta_generic_to_shared(smh);
    const unsigned sbK = sb + 16384u;    // two 16KB K slots
    const unsigned sbV = sb + 49152u;    // two 16KB V slots

    const __half* Qg = Qg_ + (size_t)bh*SEQ*DK + (size_t)qt*8192;
    const __half* Kg = Kg_ + (size_t)bh*SEQ*DK;
    const __half* Vg = Vg_ + (size_t)bh*SEQ*DK;

    auto issueKV = [&](int j){
        if (j <= qt){
            const __half* Kj = Kg + (size_t)j*8192;
            const __half* Vj = Vg + (size_t)j*8192;
            const unsigned dK = sbK + (unsigned)(j&1)*16384u;
            const unsigned dV = sbV + (unsigned)(j&1)*16384u;
            #pragma unroll
            for (int i=0;i<8;++i){
                int idx = tid + i*128, r = idx>>4, g = idx&15;
                unsigned sw = (unsigned)((g&8)|((g&7)^(r&7)));
                cpa(dK + (unsigned)(r*256) + sw*16u, Kj + r*128 + g*8);
                cpa(dV + (unsigned)(r*256) + sw*16u, Vj + r*128 + g*8);
            }
        }
        cpcommit();
    };
    issueKV(0);
    issueKV(1);

    // stage Q (fp16 global -> swizzled smem), 64 rows
    #pragma unroll
    for (int i=0;i<8;++i){
        int idx = tid + i*128, r = idx>>4, g = idx&15;
        int sw = (g&8)|((g&7)^(r&7));
        *(uint4*)&sQh[r*128 + sw*8] = *(const uint4*)(Qg + r*128 + g*8);
    }
    __syncthreads();

    // hoist Q fragments (reused across all kv tiles)
    unsigned qf[8][4];
    #pragma unroll
    for (int ks=0;ks<8;++ks){
        const int row = wrow + (lane & 15);
        const int h   = ks*16 + (lane>>4)*8;
        ldsm4(qf[ks], sb + 2u*(unsigned)swh(row, h));
    }

    float m0=-1e30f, m1=-1e30f, l0=0.f, l1=0.f;
    float O[16][4];
    #pragma unroll
    for (int nt=0; nt<16; ++nt){ O[nt][0]=0.f; O[nt][1]=0.f; O[nt][2]=0.f; O[nt][3]=0.f; }

    for (int j = 0; j <= qt; ++j){
        cpwait<1>();
        __syncthreads();
        const unsigned bK = sbK + (unsigned)(j&1)*16384u;
        const unsigned bV = sbV + (unsigned)(j&1)*16384u;

        // S = Q K^T  (64 kv cols; Q pre-scaled; pairwise ldsm)
        float S[8][4];
        #pragma unroll
        for (int nt=0; nt<8; ++nt){ S[nt][0]=0.f; S[nt][1]=0.f; S[nt][2]=0.f; S[nt][3]=0.f; }
        #pragma unroll
        for (int ks=0; ks<8; ++ks){
            #pragma unroll
            for (int np=0; np<4; np+=2){
                unsigned k0[4], k1[4];
                const int row0 = np*16 + ((lane>>4)<<3) + (lane&7);
                const int h    = ks*16 + ((lane>>3)&1)*8;
                ldsm4(k0, bK + 2u*(unsigned)swh(row0,      h));
                ldsm4(k1, bK + 2u*(unsigned)swh(row0 + 16, h));
                mma16(S[2*np],   qf[ks][0],qf[ks][1],qf[ks][2],qf[ks][3], k0[0], k0[1]);
                mma16(S[2*np+1], qf[ks][0],qf[ks][1],qf[ks][2],qf[ks][3], k0[2], k0[3]);
                mma16(S[2*np+2], qf[ks][0],qf[ks][1],qf[ks][2],qf[ks][3], k1[0], k1[1]);
                mma16(S[2*np+3], qf[ks][0],qf[ks][1],qf[ks][2],qf[ks][3], k1[2], k1[3]);
            }
        }

        // causal mask on diagonal tile
        if (j == qt){
            #pragma unroll
            for (int nt=0; nt<8; ++nt){
                const int c0 = nt*8 + 2*lk, c1 = c0 + 1;
                const int r0 = wrow + lr,   r1 = r0 + 8;
                if (c0 > r0) S[nt][0] = -1e30f;
                if (c1 > r0) S[nt][1] = -1e30f;
                if (c0 > r1) S[nt][2] = -1e30f;
                if (c1 > r1) S[nt][3] = -1e30f;
            }
        }

        // online softmax: fp32 max-reduce, then f16x2 ex2 (P lands packed for PV)
        float mx0 = -1e30f, mx1 = -1e30f;
        #pragma unroll
        for (int nt=0; nt<8; ++nt){
            mx0 = fmaxf(mx0, fmaxf(S[nt][0], S[nt][1]));
            mx1 = fmaxf(mx1, fmaxf(S[nt][2], S[nt][3]));
        }
        mx0 = fmaxf(mx0, __shfl_xor_sync(0xffffffffu, mx0, 1));
        mx0 = fmaxf(mx0, __shfl_xor_sync(0xffffffffu, mx0, 2));
        mx1 = fmaxf(mx1, __shfl_xor_sync(0xffffffffu, mx1, 1));
        mx1 = fmaxf(mx1, __shfl_xor_sync(0xffffffffu, mx1, 2));
        const float nm0 = fmaxf(m0, mx0), nm1 = fmaxf(m1, mx1);
        const float f0 = ex2f(m0 - nm0), f1 = ex2f(m1 - nm1);
        m0 = nm0; m1 = nm1;

        unsigned Ph[8][2];
        #pragma unroll
        for (int nt=0; nt<8; ++nt){
            Ph[nt][0] = hex2(packh2(S[nt][0] - nm0, S[nt][1] - nm0));
            Ph[nt][1] = hex2(packh2(S[nt][2] - nm1, S[nt][3] - nm1));
        }

        #pragma unroll
        for (int nt=0; nt<16; ++nt){
            O[nt][0] *= f0; O[nt][1] *= f0; O[nt][2] *= f1; O[nt][3] *= f1;
        }

        // O += P @ V ; row-sum l via ones-MMA (fp32 accum, consistent with PV)
        float Lacc[4] = {0.f, 0.f, 0.f, 0.f};
        #pragma unroll
        for (int kk=0; kk<4; ++kk){
            const unsigned a0 = Ph[2*kk][0],   a1 = Ph[2*kk][1];
            const unsigned a2 = Ph[2*kk+1][0], a3 = Ph[2*kk+1][1];
            mma16(Lacc, a0,a1,a2,a3, ONES, ONES);
            #pragma unroll
            for (int np=0; np<8; np+=2){
                unsigned v0[4], v1[4];
                const int row = kk*16 + ((lane>>3)&1)*8 + (lane&7);
                const int d0  = np*16 + ((lane>>4)<<3);
                ldsm4t(v0, bV + 2u*(unsigned)swh(row, d0));
                ldsm4t(v1, bV + 2u*(unsigned)swh(row, d0 + 16));
                mma16(O[2*np],   a0,a1,a2,a3, v0[0], v0[1]);
                mma16(O[2*np+1], a0,a1,a2,a3, v0[2], v0[3]);
                mma16(O[2*np+2], a0,a1,a2,a3, v1[0], v1[1]);
                mma16(O[2*np+3], a0,a1,a2,a3, v1[2], v1[3]);
            }
        }
        l0 = l0*f0 + Lacc[0];
        l1 = l1*f1 + Lacc[2];

        __syncthreads();          // all warps done with slot (j&1)
        issueKV(j+2);             // refill freed slot (empty commit past end)
    }

    // epilogue: normalize, write fp16 Y[b, t, h*128 + d]
    const float inv0 = 1.f / l0, inv1 = 1.f / l1;
    const int rg = qt*64 + wrow + lr;
    const size_t base = ((size_t)(bh>>4)*SEQ + rg)*CDIM + (bh&15)*DK;
    #pragma unroll
    for (int nt=0; nt<16; ++nt){
        *(unsigned*)(Yg + base + nt*8 + 2*lk) = packh2(O[nt][0]*inv0, O[nt][1]*inv0);
        *(unsigned*)(Yg + base + (size_t)8*CDIM + nt*8 + 2*lk) = packh2(O[nt][2]*inv1, O[nt][3]*inv1);
    }
}

extern "C" void kernel_launch(void* const* d_in, const int* in_sizes, int n_in,
                              void* d_out, int out_size)
{
    const float* x      = (const float*)d_in[0];
    const float* w_attn = (const float*)d_in[1];
    const float* b_attn = (const float*)d_in[2];
    const float* w_proj = (const float*)d_in[3];
    const float* b_proj = (const float*)d_in[4];

    float* yOut = (float*)d_out;
    float* kOut = yOut + (size_t)BTC;
    float* vOut = yOut + (size_t)2*BTC;

    __half *Xh, *WAh, *WPh, *Qh, *Kh, *Vh, *Yh;
    cudaGetSymbolAddress((void**)&Xh,  g_Xh);
    cudaGetSymbolAddress((void**)&WAh, g_WAh);
    cudaGetSymbolAddress((void**)&WPh, g_WPh);
    cudaGetSymbolAddress((void**)&Qh,  g_Qh);
    cudaGetSymbolAddress((void**)&Kh,  g_Kh);
    cudaGetSymbolAddress((void**)&Vh,  g_Vh);
    cudaGetSymbolAddress((void**)&Yh,  g_Yh);

    const int smemG = 98304;    // 3 stages x 32KB
    const int smemF = 81920;    // Q 16K + K 2x16K + V 2x16K
    cudaFuncSetAttribute((const void*)gemm_h<0>, cudaFuncAttributeMaxDynamicSharedMemorySize, smemG);
    cudaFuncSetAttribute((const void*)gemm_h<1>, cudaFuncAttributeMaxDynamicSharedMemorySize, smemG);
    cudaFuncSetAttribute((const void*)flash_attn, cudaFuncAttributeMaxDynamicSharedMemorySize, smemF);

    // 0) fused one-time fp16 conversions (x | w_attn | w_proj)
    cvt_all<<<16384, 256>>>(x, w_attn, w_proj, Xh, WAh, WPh);

    // 1) QKV = x @ w_attn^T + b_attn  (M=8192, N=6144, K=2048), 4-warp CTAs
    gemm_h<0><<<dim3(48,64), 128, smemG>>>(Xh, WAh, b_attn,
                                           nullptr, kOut, vOut, Qh, Kh, Vh);

    // 2) fused flash attention: 64-row q-tiles, 2 CTA/SM  -> fp16 Yh
    flash_attn<<<dim3(64,32), 128, smemF>>>(Qh, Kh, Vh, Yh);

    // 3) y = Y @ w_proj^T + b_proj   (M=8192, N=2048, K=2048), 4-warp CTAs
    gemm_h<1><<<dim3(16,64), 128, smemG>>>(Yh, WPh, b_proj,
                                           yOut, nullptr, nullptr, nullptr, nullptr, nullptr);
}